// round 3
// baseline (speedup 1.0000x reference)
#include <cuda_runtime.h>
#include <math.h>

// LSTM: T=512, B=64, I=H=512.  out[t,b,h] = h_t.
// Kernel 1: x_proj[t][g*512+h][b] = x @ W_ih^T + (b_ih + b_hh)
// Kernel 2: persistent 128-CTA recurrence, CTA = (b-quarter x 16 hc),
//           thread = one (b,hc): 4 full-K gate dots, no reduction step.

#define Tq 512
#define Bq 64
#define Hq 512
#define G4 2048
#define REC_NCTA 128
#define WSTR 516                 // padded row stride (floats), float4-aligned
#define WSTR4 129

typedef unsigned long long ull;

__device__ float g_xp[(size_t)Tq * G4 * Bq];   // 256MB scratch
__device__ unsigned g_count = 0;               // monotonic barrier counter

__device__ __forceinline__ ull pk2(float lo, float hi) {
    ull r; asm("mov.b64 %0, {%1, %2};" : "=l"(r) : "f"(lo), "f"(hi)); return r;
}
__device__ __forceinline__ float2 upk2(ull v) {
    float2 r; asm("mov.b64 {%0, %1}, %2;" : "=f"(r.x), "=f"(r.y) : "l"(v)); return r;
}
__device__ __forceinline__ ull ffma2(ull a, ull b, ull c) {
    ull d; asm("fma.rn.f32x2 %0, %1, %2, %3;" : "=l"(d) : "l"(a), "l"(b), "l"(c)); return d;
}
__device__ __forceinline__ void cpa16(float* s, const float* g) {
    unsigned sa = (unsigned)__cvta_generic_to_shared(s);
    asm volatile("cp.async.cg.shared.global [%0], [%1], 16;" :: "r"(sa), "l"(g));
}
__device__ __forceinline__ void cpcommit() { asm volatile("cp.async.commit_group;"); }
template <int N> __device__ __forceinline__ void cpwait() {
    asm volatile("cp.async.wait_group %0;" :: "n"(N));
}
__device__ __forceinline__ float sigf(float x) {
    return __fdividef(1.f, 1.f + __expf(-x));
}
__device__ __forceinline__ float tanhx(float x) {
    return __fdividef(2.f, 1.f + __expf(-2.f * x)) - 1.f;
}

// ---------------------------------------------------------------------------
// Kernel 1: C[M=32768, N=2048] = x[M,512] * W_ih[N,512]^T + bias
// ---------------------------------------------------------------------------
__global__ __launch_bounds__(256, 2) void gemm_xproj(
    const float* __restrict__ A, const float* __restrict__ W,
    const float* __restrict__ bih, const float* __restrict__ bhh)
{
    __shared__ float As[16][128];
    __shared__ float Bs[16][128];
    const int tid = threadIdx.x;
    const int m0 = blockIdx.y * 128;
    const int n0 = blockIdx.x * 128;
    const int lrow = tid >> 1;
    const int lc = (tid & 1) * 8;
    const int tmq = tid & 15;
    const int tn = (tid >> 4) * 8;

    const float* Ap = A + (size_t)(m0 + lrow) * 512 + lc;
    const float* Bp = W + (size_t)(n0 + lrow) * 512 + lc;

    ull acc[8][4];
#pragma unroll
    for (int j = 0; j < 8; j++)
#pragma unroll
        for (int p = 0; p < 4; p++) acc[j][p] = 0ull;

    float4 a0 = *(const float4*)(Ap);
    float4 a1 = *(const float4*)(Ap + 4);
    float4 b0 = *(const float4*)(Bp);
    float4 b1 = *(const float4*)(Bp + 4);

    const float4* As4 = (const float4*)As;
    const float4* Bs4 = (const float4*)Bs;

#pragma unroll 1
    for (int k0 = 0; k0 < 512; k0 += 16) {
        __syncthreads();
        As[lc + 0][lrow] = a0.x; As[lc + 1][lrow] = a0.y;
        As[lc + 2][lrow] = a0.z; As[lc + 3][lrow] = a0.w;
        As[lc + 4][lrow] = a1.x; As[lc + 5][lrow] = a1.y;
        As[lc + 6][lrow] = a1.z; As[lc + 7][lrow] = a1.w;
        Bs[lc + 0][lrow] = b0.x; Bs[lc + 1][lrow] = b0.y;
        Bs[lc + 2][lrow] = b0.z; Bs[lc + 3][lrow] = b0.w;
        Bs[lc + 4][lrow] = b1.x; Bs[lc + 5][lrow] = b1.y;
        Bs[lc + 6][lrow] = b1.z; Bs[lc + 7][lrow] = b1.w;
        __syncthreads();
        if (k0 + 16 < 512) {
            a0 = *(const float4*)(Ap + k0 + 16);
            a1 = *(const float4*)(Ap + k0 + 20);
            b0 = *(const float4*)(Bp + k0 + 16);
            b1 = *(const float4*)(Bp + k0 + 20);
        }
#pragma unroll 8
        for (int kk = 0; kk < 16; kk++) {
            float4 av0 = As4[kk * 32 + tmq];
            float4 av1 = As4[kk * 32 + 16 + tmq];
            ull am[4] = { pk2(av0.x, av0.y), pk2(av0.z, av0.w),
                          pk2(av1.x, av1.y), pk2(av1.z, av1.w) };
            float4 bv0 = Bs4[kk * 32 + (tid >> 4) * 2];
            float4 bv1 = Bs4[kk * 32 + (tid >> 4) * 2 + 1];
            float bb[8] = { bv0.x, bv0.y, bv0.z, bv0.w, bv1.x, bv1.y, bv1.z, bv1.w };
#pragma unroll
            for (int j = 0; j < 8; j++) {
                ull bd = pk2(bb[j], bb[j]);
#pragma unroll
                for (int p = 0; p < 4; p++) acc[j][p] = ffma2(bd, am[p], acc[j][p]);
            }
        }
    }

#pragma unroll
    for (int j = 0; j < 8; j++) {
        int n = n0 + tn + j;
        float bv = bih[n] + bhh[n];
#pragma unroll
        for (int p = 0; p < 4; p++) {
            float2 v = upk2(acc[j][p]);
            v.x += bv; v.y += bv;
            int m = m0 + tmq * 4 + (p & 1) * 2 + (p >> 1) * 64;
            int tt = m >> 6, bb2 = m & 63;
            *(float2*)&g_xp[((size_t)tt * G4 + n) * Bq + bb2] = v;
        }
    }
}

// ---------------------------------------------------------------------------
// Kernel 2: persistent recurrence, grid 128 = (bq 0..3) x (hg 0..31).
// CTA covers b in [bq*16,+16), hc in [hg*16,+16). 256 threads: one (b,hc) each.
// Smem: W_hh slice 64 rows (hc,g) x 512 (loaded once), h slab 16 x 512 staged
// per step in 4 pipelined cp.async chunks of K=128.
// ---------------------------------------------------------------------------
__global__ __launch_bounds__(256, 1) void lstm_rec(
    const float* __restrict__ Whh, float* __restrict__ out)
{
    extern __shared__ float sm[];
    float* Ws = sm;                         // [64 rows = hcl*4+g][WSTR]
    float* hs = sm + 64 * WSTR;             // [16 b][WSTR]
    float* ho = hs + 16 * WSTR;             // [16 b][16 hc] staging for out
    const int tid = threadIdx.x;
    const int bl = tid & 15;                // local batch
    const int hcl = tid >> 4;               // local h-column
    const int bq = blockIdx.x >> 5;         // 0..3
    const int hg = blockIdx.x & 31;         // 0..31
    const int b0 = bq * 16;
    const int hc0 = hg * 16;
    const int hcE = hc0 + hcl;
    const int bE = b0 + bl;

    // load W_hh slice once: row r = hcl*4+g  <-  Whh[g*512 + hc0 + hcl][k]
    for (int i = tid; i < 64 * 128; i += 256) {
        int r = i >> 7;                     // 0..63
        int c4 = i & 127;
        int grow = (r & 3) * 512 + hc0 + (r >> 2);
        ((float4*)(Ws + r * WSTR))[c4] = ((const float4*)(Whh + (size_t)grow * 512))[c4];
    }
    __syncthreads();

    const float4* hp4 = (const float4*)hs + bl * WSTR4;
    const float4* w0p = (const float4*)Ws + (hcl * 4 + 0) * WSTR4;
    const float4* w1p = (const float4*)Ws + (hcl * 4 + 1) * WSTR4;
    const float4* w2p = (const float4*)Ws + (hcl * 4 + 2) * WSTR4;
    const float4* w3p = (const float4*)Ws + (hcl * 4 + 3) * WSTR4;
    float cst = 0.f;

#pragma unroll 1
    for (int t = 0; t < Tq; t++) {
        // x_proj for this (b,hc), issued early
        const float* xpt = g_xp + (size_t)t * (G4 * Bq) + (size_t)hcE * Bq + bE;
        float g0 = __ldg(xpt + 0 * 512 * Bq);
        float g1 = __ldg(xpt + 1 * 512 * Bq);
        float g2 = __ldg(xpt + 2 * 512 * Bq);
        float g3 = __ldg(xpt + 3 * 512 * Bq);

        if (t > 0) {
            const float* hp = out + (size_t)(t - 1) * (Bq * Hq) + (size_t)b0 * Hq;
            // issue chunk 0 (K 0..127): 512 float4, 2 per thread
#pragma unroll
            for (int r = 0; r < 2; r++) {
                int j = tid + r * 256;
                int row = j >> 5, kf = j & 31;
                cpa16(hs + row * WSTR + kf * 4, hp + row * 512 + kf * 4);
            }
            cpcommit();

            ull a0 = 0, a1 = 0, a2 = 0, a3 = 0;
#pragma unroll 1
            for (int c = 0; c < 4; c++) {
                if (c < 3) {                 // issue chunk c+1, wait chunk c
                    int kb = (c + 1) * 128;
#pragma unroll
                    for (int r = 0; r < 2; r++) {
                        int j = tid + r * 256;
                        int row = j >> 5, kf = j & 31;
                        cpa16(hs + row * WSTR + kb + kf * 4, hp + row * 512 + kb + kf * 4);
                    }
                    cpcommit();
                    cpwait<1>();
                } else {
                    cpwait<0>();
                }
                __syncthreads();
                int kb4 = c * 32;
#pragma unroll 8
                for (int k4 = 0; k4 < 32; k4++) {
                    float4 h4 = hp4[kb4 + k4];
                    ull h01 = pk2(h4.x, h4.y), h23 = pk2(h4.z, h4.w);
                    float4 w0 = w0p[kb4 + k4];
                    float4 w1 = w1p[kb4 + k4];
                    float4 w2 = w2p[kb4 + k4];
                    float4 w3 = w3p[kb4 + k4];
                    a0 = ffma2(h01, pk2(w0.x, w0.y), a0);
                    a1 = ffma2(h01, pk2(w1.x, w1.y), a1);
                    a2 = ffma2(h01, pk2(w2.x, w2.y), a2);
                    a3 = ffma2(h01, pk2(w3.x, w3.y), a3);
                    a0 = ffma2(h23, pk2(w0.z, w0.w), a0);
                    a1 = ffma2(h23, pk2(w1.z, w1.w), a1);
                    a2 = ffma2(h23, pk2(w2.z, w2.w), a2);
                    a3 = ffma2(h23, pk2(w3.z, w3.w), a3);
                }
                if (c < 3) __syncthreads();  // chunk c consumed before next wait
            }
            float2 v0 = upk2(a0), v1 = upk2(a1), v2 = upk2(a2), v3 = upk2(a3);
            g0 += v0.x + v0.y;
            g1 += v1.x + v1.y;
            g2 += v2.x + v2.y;
            g3 += v3.x + v3.y;
        }

        float iv = sigf(g0);
        float fv = sigf(g1);
        float gv = tanhx(g2);
        float ov = sigf(g3);
        cst = fv * cst + iv * gv;
        float hv = ov * tanhx(cst);

        // stage h through smem, write coalesced float4
        ho[bl * 16 + hcl] = hv;
        __syncthreads();
        if (tid < 64) {
            int row = tid >> 2, f4 = tid & 3;
            float4 v = ((const float4*)(ho + row * 16))[f4];
            *(float4*)&out[(size_t)t * (Bq * Hq) + (size_t)(b0 + row) * Hq + hc0 + f4 * 4] = v;
        }

        if (t < Tq - 1) {
            __syncthreads();
            if (tid == 0) {
                unsigned old;
                asm volatile("atom.release.gpu.add.u32 %0, [%1], 1;"
                             : "=r"(old) : "l"(&g_count) : "memory");
                unsigned target = (unsigned)REC_NCTA * (unsigned)(t + 1);
                unsigned v = old + 1;
                while (v < target) {
                    asm volatile("ld.acquire.gpu.u32 %0, [%1];"
                                 : "=r"(v) : "l"(&g_count) : "memory");
                }
            }
            __syncthreads();
        }
    }

    // final arrive: last CTA resets counter for next graph replay
    if (tid == 0) {
        unsigned old = atomicAdd(&g_count, 1u);
        if (old == (unsigned)REC_NCTA * (unsigned)Tq - 1u)
            *((volatile unsigned*)&g_count) = 0u;
    }
}

#define REC_SMEM ((64 * WSTR + 16 * WSTR + 16 * 16) * 4)

extern "C" void kernel_launch(void* const* d_in, const int* in_sizes, int n_in,
                              void* d_out, int out_size) {
    const float* x   = (const float*)d_in[0];   // [512,64,512]
    const float* Wih = (const float*)d_in[1];   // [2048,512]
    const float* Whh = (const float*)d_in[2];   // [2048,512]
    const float* bih = (const float*)d_in[3];   // [2048]
    const float* bhh = (const float*)d_in[4];   // [2048]
    float* out = (float*)d_out;                 // [512,64,512]

    cudaFuncSetAttribute(lstm_rec, cudaFuncAttributeMaxDynamicSharedMemorySize, REC_SMEM);

    dim3 g1(G4 / 128, (Tq * Bq) / 128);         // (16, 256)
    gemm_xproj<<<g1, 256>>>(x, Wih, bih, bhh);
    lstm_rec<<<REC_NCTA, 256, REC_SMEM>>>(Whh, out);
}